// round 3
// baseline (speedup 1.0000x reference)
#include <cuda_runtime.h>
#include <cuda_bf16.h>
#include <cstdint>

// out[s,a] = values[index[s,a]]
// index: int32 [33,554,432], values: float [100], out: float [33,554,432]
//
// HBM-bound gather. This round:
//  - table replicated 32x in smem (one copy per bank) -> conflict-free LDS
//  - MLP = 8 front-batched int4 loads per thread
//  - streaming cache hints on both global streams

static constexpr int VOCAB_MAX       = 100;
static constexpr int THREADS         = 256;
static constexpr int VEC_PER_THREAD  = 8;                        // 8 x int4 = 32 elems/thread
static constexpr int VEC_PER_BLOCK   = THREADS * VEC_PER_THREAD; // 2048 vec4 / block

__global__ void __launch_bounds__(THREADS) gather_vec4x8_kernel(
    const int4* __restrict__ idx4,
    const float* __restrict__ values,
    float4* __restrict__ out4,
    int n_vec4,
    int n_values)
{
    // 32 replicas of the table, one per smem bank.
    // Layout: s_vals[v * 32 + lane] -> bank = lane -> conflict-free.
    __shared__ float s_vals[VOCAB_MAX * 32];

    const int n_rep = n_values * 32;
    for (int i = threadIdx.x; i < n_rep; i += THREADS) {
        s_vals[i] = values[i >> 5];   // values[i / 32], broadcast reads hit L1
    }
    __syncthreads();

    const unsigned lane = threadIdx.x & 31u;
    int base = blockIdx.x * VEC_PER_BLOCK + threadIdx.x;

    if (base + (VEC_PER_THREAD - 1) * THREADS < n_vec4) {
        // Fast path: fully in range (all blocks for this shape:
        // 8,388,608 / 2048 = 4096 blocks exactly).
        int4 v[VEC_PER_THREAD];
        #pragma unroll
        for (int k = 0; k < VEC_PER_THREAD; k++) {
            v[k] = __ldcs(&idx4[base + k * THREADS]);
        }
        #pragma unroll
        for (int k = 0; k < VEC_PER_THREAD; k++) {
            float4 r;
            r.x = s_vals[((unsigned)v[k].x << 5) | lane];
            r.y = s_vals[((unsigned)v[k].y << 5) | lane];
            r.z = s_vals[((unsigned)v[k].z << 5) | lane];
            r.w = s_vals[((unsigned)v[k].w << 5) | lane];
            __stcs(&out4[base + k * THREADS], r);
        }
    } else {
        // Tail path (unused for this shape, kept for safety)
        #pragma unroll
        for (int k = 0; k < VEC_PER_THREAD; k++) {
            int i = base + k * THREADS;
            if (i < n_vec4) {
                int4 v = __ldcs(&idx4[i]);
                float4 r;
                r.x = s_vals[((unsigned)v.x << 5) | lane];
                r.y = s_vals[((unsigned)v.y << 5) | lane];
                r.z = s_vals[((unsigned)v.z << 5) | lane];
                r.w = s_vals[((unsigned)v.w << 5) | lane];
                __stcs(&out4[i], r);
            }
        }
    }
}

__global__ void gather_tail_kernel(
    const int* __restrict__ idx,
    const float* __restrict__ values,
    float* __restrict__ out,
    int start,
    int n_total)
{
    int i = start + blockIdx.x * blockDim.x + threadIdx.x;
    if (i < n_total) {
        out[i] = values[idx[i]];
    }
}

extern "C" void kernel_launch(void* const* d_in, const int* in_sizes, int n_in,
                              void* d_out, int out_size)
{
    const int* index = (const int*)d_in[0];
    const float* values = (const float*)d_in[1];
    float* out = (float*)d_out;

    int n_total = in_sizes[0];          // 33,554,432
    int n_values = in_sizes[1];         // 100
    int n_vec4 = n_total / 4;           // 8,388,608

    int blocks = (n_vec4 + VEC_PER_BLOCK - 1) / VEC_PER_BLOCK;   // 4096
    gather_vec4x8_kernel<<<blocks, THREADS>>>(
        (const int4*)index, values, (float4*)out, n_vec4, n_values);

    int tail_start = n_vec4 * 4;
    int tail = n_total - tail_start;
    if (tail > 0) {
        int tb = (tail + 255) / 256;
        gather_tail_kernel<<<tb, 256>>>(index, values, out, tail_start, n_total);
    }
}

// round 4
// speedup vs baseline: 1.0142x; 1.0142x over previous
#include <cuda_runtime.h>
#include <cuda_bf16.h>
#include <cstdint>

// out[s,a] = values[index[s,a]]
// index: int32 [33,554,432], values: float [100], out: float [33,554,432]
//
// HBM-bound gather near the mixed R/W roofline. Recipe:
//  - tiny single-copy table in smem (512 B -> zero occupancy cost)
//  - 8 front-batched independent int4 loads per thread (MLP = 8)
//  - streaming cache hints on both global streams

static constexpr int VOCAB_MAX       = 128;
static constexpr int THREADS         = 256;
static constexpr int VEC_PER_THREAD  = 8;                        // 8 x int4 = 32 elems/thread
static constexpr int VEC_PER_BLOCK   = THREADS * VEC_PER_THREAD; // 2048 vec4/block

__global__ void __launch_bounds__(THREADS) gather_vec4x8s_kernel(
    const int4* __restrict__ idx4,
    const float* __restrict__ values,
    float4* __restrict__ out4,
    int n_vec4,
    int n_values)
{
    __shared__ float s_vals[VOCAB_MAX];
    for (int i = threadIdx.x; i < n_values; i += THREADS) {
        s_vals[i] = values[i];
    }
    __syncthreads();

    int base = blockIdx.x * VEC_PER_BLOCK + threadIdx.x;

    if (base + (VEC_PER_THREAD - 1) * THREADS < n_vec4) {
        // Fast path: all blocks for this shape (8,388,608 / 2048 = 4096 exactly).
        int4 v[VEC_PER_THREAD];
        #pragma unroll
        for (int k = 0; k < VEC_PER_THREAD; k++) {
            v[k] = __ldcs(&idx4[base + k * THREADS]);
        }
        #pragma unroll
        for (int k = 0; k < VEC_PER_THREAD; k++) {
            float4 r;
            r.x = s_vals[v[k].x];
            r.y = s_vals[v[k].y];
            r.z = s_vals[v[k].z];
            r.w = s_vals[v[k].w];
            __stcs(&out4[base + k * THREADS], r);
        }
    } else {
        // Tail path (unused for this shape, kept for safety)
        #pragma unroll
        for (int k = 0; k < VEC_PER_THREAD; k++) {
            int i = base + k * THREADS;
            if (i < n_vec4) {
                int4 v = __ldcs(&idx4[i]);
                float4 r;
                r.x = s_vals[v.x];
                r.y = s_vals[v.y];
                r.z = s_vals[v.z];
                r.w = s_vals[v.w];
                __stcs(&out4[i], r);
            }
        }
    }
}

__global__ void gather_tail_kernel(
    const int* __restrict__ idx,
    const float* __restrict__ values,
    float* __restrict__ out,
    int start,
    int n_total)
{
    int i = start + blockIdx.x * blockDim.x + threadIdx.x;
    if (i < n_total) {
        out[i] = values[idx[i]];
    }
}

extern "C" void kernel_launch(void* const* d_in, const int* in_sizes, int n_in,
                              void* d_out, int out_size)
{
    const int* index = (const int*)d_in[0];
    const float* values = (const float*)d_in[1];
    float* out = (float*)d_out;

    int n_total = in_sizes[0];          // 33,554,432
    int n_values = in_sizes[1];         // 100
    int n_vec4 = n_total / 4;           // 8,388,608

    int blocks = (n_vec4 + VEC_PER_BLOCK - 1) / VEC_PER_BLOCK;   // 4096
    gather_vec4x8s_kernel<<<blocks, THREADS>>>(
        (const int4*)index, values, (float4*)out, n_vec4, n_values);

    int tail_start = n_vec4 * 4;
    int tail = n_total - tail_start;
    if (tail > 0) {
        int tb = (tail + 255) / 256;
        gather_tail_kernel<<<tb, 256>>>(index, values, out, tail_start, n_total);
    }
}

// round 5
// speedup vs baseline: 1.0522x; 1.0375x over previous
#include <cuda_runtime.h>
#include <cuda_bf16.h>
#include <cstdint>

// out[s,a] = values[index[s,a]]
// index: int32 [33,554,432], values: float [100], out: float [33,554,432]
//
// HBM-bound gather, converged recipe (R2-class):
//  - tiny single-copy 512B table in smem (zero occupancy cost)
//  - MLP = 4 front-batched int4 loads per thread (32 regs -> full occupancy;
//    MLP=8 measured worse: +8 regs cost more occupancy than latency it hid)
//  - 512 threads/block: half the CTAs -> less fill/barrier overhead
//  - streaming cache hints on both touch-once global streams

static constexpr int VOCAB_MAX       = 128;
static constexpr int THREADS         = 512;
static constexpr int VEC_PER_THREAD  = 4;                        // 4 x int4 = 16 elems/thread
static constexpr int VEC_PER_BLOCK   = THREADS * VEC_PER_THREAD; // 2048 vec4/block

__global__ void __launch_bounds__(THREADS) gather_vec4x4w_kernel(
    const int4* __restrict__ idx4,
    const float* __restrict__ values,
    float4* __restrict__ out4,
    int n_vec4,
    int n_values)
{
    __shared__ float s_vals[VOCAB_MAX];
    for (int i = threadIdx.x; i < n_values; i += THREADS) {
        s_vals[i] = values[i];
    }
    __syncthreads();

    int base = blockIdx.x * VEC_PER_BLOCK + threadIdx.x;

    if (base + (VEC_PER_THREAD - 1) * THREADS < n_vec4) {
        // Fast path: all blocks for this shape (8,388,608 / 2048 = 4096 exactly).
        int4 v[VEC_PER_THREAD];
        #pragma unroll
        for (int k = 0; k < VEC_PER_THREAD; k++) {
            v[k] = __ldcs(&idx4[base + k * THREADS]);
        }
        #pragma unroll
        for (int k = 0; k < VEC_PER_THREAD; k++) {
            float4 r;
            r.x = s_vals[v[k].x];
            r.y = s_vals[v[k].y];
            r.z = s_vals[v[k].z];
            r.w = s_vals[v[k].w];
            __stcs(&out4[base + k * THREADS], r);
        }
    } else {
        // Tail path (unused for this shape, kept for safety)
        #pragma unroll
        for (int k = 0; k < VEC_PER_THREAD; k++) {
            int i = base + k * THREADS;
            if (i < n_vec4) {
                int4 v = __ldcs(&idx4[i]);
                float4 r;
                r.x = s_vals[v.x];
                r.y = s_vals[v.y];
                r.z = s_vals[v.z];
                r.w = s_vals[v.w];
                __stcs(&out4[i], r);
            }
        }
    }
}

__global__ void gather_tail_kernel(
    const int* __restrict__ idx,
    const float* __restrict__ values,
    float* __restrict__ out,
    int start,
    int n_total)
{
    int i = start + blockIdx.x * blockDim.x + threadIdx.x;
    if (i < n_total) {
        out[i] = values[idx[i]];
    }
}

extern "C" void kernel_launch(void* const* d_in, const int* in_sizes, int n_in,
                              void* d_out, int out_size)
{
    const int* index = (const int*)d_in[0];
    const float* values = (const float*)d_in[1];
    float* out = (float*)d_out;

    int n_total = in_sizes[0];          // 33,554,432
    int n_values = in_sizes[1];         // 100
    int n_vec4 = n_total / 4;           // 8,388,608

    int blocks = (n_vec4 + VEC_PER_BLOCK - 1) / VEC_PER_BLOCK;   // 4096
    gather_vec4x4w_kernel<<<blocks, THREADS>>>(
        (const int4*)index, values, (float4*)out, n_vec4, n_values);

    int tail_start = n_vec4 * 4;
    int tail = n_total - tail_start;
    if (tail > 0) {
        int tb = (tail + 255) / 256;
        gather_tail_kernel<<<tb, 256>>>(index, values, out, tail_start, n_total);
    }
}